// round 10
// baseline (speedup 1.0000x reference)
#include <cuda_runtime.h>
#include <math.h>

// ChamferLoss: B=8, N=M=4096, D=3 — global bin-sort once, then smem-copy + pruned NN.

#define BATCH    8
#define NPTS     4096
#define NCLOUD   16                        // 8 batches x {pred, targ}
#define NBINS    128
#define XMIN     (-3.2f)
#define BINW     0.05f
#define INV_BINW 20.0f
#define THREADS  256
#define SLICES   16                        // source slices per combo
#define NCOMBO   16
#define NBLOCKS  (NCOMBO * SLICES)         // 256
#define NWARPS   (THREADS / 32)

__device__ float4 g_sorted[NCLOUD][NPTS];        // (x,y,z,|t|^2), x-bin-sorted
__device__ int    g_binstart[NCLOUD][NBINS + 1];
__device__ double g_sum  = 0.0;
__device__ unsigned int g_tick = 0;

static __device__ __forceinline__ int bin_of(float x) {
    int b = (int)((x - XMIN) * INV_BINW);
    return min(max(b, 0), NBINS - 1);
}

// ---------------- Kernel 1: sort each cloud once ----------------
__global__ __launch_bounds__(256) void sort_kernel(
    const float* __restrict__ pred,
    const float* __restrict__ targ)
{
    __shared__ int cnt[NBINS];
    __shared__ int ofs[NBINS];

    const int c = blockIdx.x;
    const int b = c >> 1;
    const float* __restrict__ src = ((c & 1) ? targ : pred) + (size_t)b * NPTS * 3;

    for (int k = threadIdx.x; k < NBINS; k += 256) cnt[k] = 0;
    __syncthreads();
    #pragma unroll
    for (int i = threadIdx.x; i < NPTS; i += 256)
        atomicAdd(&cnt[bin_of(src[3 * i])], 1);
    __syncthreads();

    if (threadIdx.x < 32) {           // warp-scan 128 bins (4 per lane)
        const int lane = threadIdx.x;
        int c0 = cnt[lane * 4], c1 = cnt[lane * 4 + 1];
        int c2 = cnt[lane * 4 + 2], c3 = cnt[lane * 4 + 3];
        int tot = c0 + c1 + c2 + c3;
        int pre = tot;
        #pragma unroll
        for (int o = 1; o < 32; o <<= 1) {
            int n = __shfl_up_sync(0xFFFFFFFFu, pre, o);
            if (lane >= o) pre += n;
        }
        pre -= tot;
        int p0 = pre, p1 = pre + c0, p2 = p1 + c1, p3 = p2 + c2;
        ofs[lane * 4] = p0; ofs[lane * 4 + 1] = p1;
        ofs[lane * 4 + 2] = p2; ofs[lane * 4 + 3] = p3;
        g_binstart[c][lane * 4] = p0; g_binstart[c][lane * 4 + 1] = p1;
        g_binstart[c][lane * 4 + 2] = p2; g_binstart[c][lane * 4 + 3] = p3;
        if (lane == 31) g_binstart[c][NBINS] = p3 + c3;
    }
    __syncthreads();

    #pragma unroll
    for (int i = threadIdx.x; i < NPTS; i += 256) {
        float x = src[3 * i + 0], y = src[3 * i + 1], z = src[3 * i + 2];
        float w = fmaf(x, x, fmaf(y, y, z * z));
        int pos = atomicAdd(&ofs[bin_of(x)], 1);
        g_sorted[c][pos] = make_float4(x, y, z, w);
    }
}

// ---------------- Kernel 2: copy + warp-uniform pruned NN ----------------
struct Smem {
    float4 tgt[NPTS];            // 64 KB sorted target cloud
    int    bst[NBINS + 1];
    float  warpsums[NWARPS];
    unsigned int s_done;
};

__global__ __launch_bounds__(THREADS) void search_kernel(float* __restrict__ out)
{
    extern __shared__ char smem_raw[];
    Smem* s = (Smem*)smem_raw;
    const int tid = threadIdx.x;

    const int combo = blockIdx.x / SLICES;
    const int slice = blockIdx.x % SLICES;
    const int b     = combo >> 1;
    const int dir   = combo & 1;
    const int cs    = b * 2 + dir;          // source cloud
    const int ct    = b * 2 + (dir ^ 1);    // target cloud

    // Coalesced copy of sorted target cloud + bin prefix into smem
    {
        const float4* __restrict__ g = g_sorted[ct];
        #pragma unroll
        for (int k = 0; k < NPTS / THREADS; k++)
            s->tgt[k * THREADS + tid] = g[k * THREADS + tid];
        if (tid <= NBINS) s->bst[tid] = g_binstart[ct][tid];
    }

    // Source point: globally sorted -> warp lanes are 32 consecutive points
    const float4 p = g_sorted[cs][slice * THREADS + tid];
    const float mx = -2.0f * p.x, my = -2.0f * p.y, mz = -2.0f * p.z;
    const float p2 = p.w;

    __syncthreads();

    float best = INFINITY;              // min of (|t|^2 - 2 p.t); d2 = best + p2

    // Phase A: warp-union own-bin range
    int blo = bin_of(p.x), bhi = blo;
    #pragma unroll
    for (int o = 16; o > 0; o >>= 1) {
        blo = min(blo, __shfl_xor_sync(0xFFFFFFFFu, blo, o));
        bhi = max(bhi, __shfl_xor_sync(0xFFFFFFFFu, bhi, o));
    }
    int sA = s->bst[blo], eA = s->bst[bhi + 1];
    while (sA == eA) {                  // rare: expand until non-empty
        blo = max(blo - 1, 0);
        bhi = min(bhi + 1, NBINS - 1);
        sA = s->bst[blo]; eA = s->bst[bhi + 1];
    }
    #pragma unroll 4
    for (int j = sA; j < eA; j++) {     // broadcast LDS
        float4 t = s->tgt[j];
        float v = fmaf(mx, t.x, fmaf(my, t.y, fmaf(mz, t.z, t.w)));
        best = fminf(best, v);
    }

    // Phase B: warp-union conservative final range; scan only delta segments
    float dcur = sqrtf(fmaxf(best + p2, 0.0f)) * 1.0001f + 1e-6f;
    int klo = min(max((int)floorf((p.x - dcur - XMIN) * INV_BINW), 0), NBINS - 1);
    int khi = min(max((int)floorf((p.x + dcur - XMIN) * INV_BINW), 0), NBINS - 1);
    #pragma unroll
    for (int o = 16; o > 0; o >>= 1) {
        klo = min(klo, __shfl_xor_sync(0xFFFFFFFFu, klo, o));
        khi = max(khi, __shfl_xor_sync(0xFFFFFFFFu, khi, o));
    }
    klo = min(klo, blo);
    khi = max(khi, bhi);
    int sB = s->bst[klo], eB = s->bst[khi + 1];
    #pragma unroll 4
    for (int j = sB; j < sA; j++) {
        float4 t = s->tgt[j];
        float v = fmaf(mx, t.x, fmaf(my, t.y, fmaf(mz, t.z, t.w)));
        best = fminf(best, v);
    }
    #pragma unroll 4
    for (int j = eA; j < eB; j++) {
        float4 t = s->tgt[j];
        float v = fmaf(mx, t.x, fmaf(my, t.y, fmaf(mz, t.z, t.w)));
        best = fminf(best, v);
    }

    float d = sqrtf(fmaxf(best + p2, 0.0f));

    // Reduction
    float acc = d;
    #pragma unroll
    for (int o = 16; o > 0; o >>= 1)
        acc += __shfl_xor_sync(0xFFFFFFFFu, acc, o);
    const int lane = tid & 31, wid = tid >> 5;
    if (lane == 0) s->warpsums[wid] = acc;
    __syncthreads();
    if (tid == 0) {
        float v = 0.0f;
        #pragma unroll
        for (int k = 0; k < NWARPS; k++) v += s->warpsums[k];
        atomicAdd(&g_sum, (double)v / ((double)BATCH * (double)NPTS));
    }

    // Ticket: last block publishes + resets
    __threadfence();
    if (tid == 0) s->s_done = atomicAdd(&g_tick, 1u);
    __syncthreads();
    if (s->s_done == NBLOCKS - 1 && tid == 0) {
        double total = atomicAdd(&g_sum, 0.0);   // atomic read
        out[0] = (float)total;
        g_sum  = 0.0;
        g_tick = 0;
    }
}

extern "C" void kernel_launch(void* const* d_in, const int* in_sizes, int n_in,
                              void* d_out, int out_size) {
    const float* pred = (const float*)d_in[0];
    const float* targ = (const float*)d_in[1];
    float* out = (float*)d_out;

    static bool attr_set = false;
    if (!attr_set) {
        cudaFuncSetAttribute(search_kernel,
                             cudaFuncAttributeMaxDynamicSharedMemorySize,
                             (int)sizeof(Smem));
        attr_set = true;
    }
    sort_kernel<<<NCLOUD, 256>>>(pred, targ);
    search_kernel<<<NBLOCKS, THREADS, sizeof(Smem)>>>(out);
}

// round 11
// speedup vs baseline: 1.2309x; 1.2309x over previous
#include <cuda_runtime.h>
#include <math.h>

// ChamferLoss: B=8, N=M=4096, D=3 — 2D-grid sort (snake order) + warp-uniform pruned NN.

#define BATCH    8
#define NPTS     4096
#define NCLOUD   16
#define GRID     32
#define NCELL    (GRID * GRID)          // 1024
#define XMIN     (-3.2f)
#define CELLW    0.2f
#define INV_CELLW 5.0f
#define THREADS  256
#define SLICES   16
#define NCOMBO   16
#define NBLOCKS  (NCOMBO * SLICES)      // 256
#define NWARPS   (THREADS / 32)

__device__ float4 g_sorted[NCLOUD][NPTS];        // (x,y,z,|t|^2), snake-cell-sorted
__device__ int    g_cellstart[NCLOUD][NCELL + 1];
__device__ double g_sum  = 0.0;
__device__ unsigned int g_tick = 0;

static __device__ __forceinline__ int clampg(int v) { return min(max(v, 0), GRID - 1); }
static __device__ __forceinline__ int cell_of(float x, float y) {
    int cx = clampg((int)((x - XMIN) * INV_CELLW));
    int cy = clampg((int)((y - XMIN) * INV_CELLW));
    int cxs = (cy & 1) ? (GRID - 1 - cx) : cx;   // snake: odd rows reversed
    return (cy << 5) | cxs;
}

// ---------------- Kernel 1: snake-cell counting sort, one block per cloud ----------------
__global__ __launch_bounds__(256) void sort_kernel(
    const float* __restrict__ pred,
    const float* __restrict__ targ)
{
    __shared__ int cnt[NCELL];
    __shared__ int ofs[NCELL];
    __shared__ int wtot[8];

    const int c = blockIdx.x;
    const int b = c >> 1;
    const float* __restrict__ src = ((c & 1) ? targ : pred) + (size_t)b * NPTS * 3;
    const int tid = threadIdx.x;

    for (int k = tid; k < NCELL; k += 256) cnt[k] = 0;
    __syncthreads();
    #pragma unroll
    for (int i = tid; i < NPTS; i += 256)
        atomicAdd(&cnt[cell_of(src[3 * i], src[3 * i + 1])], 1);
    __syncthreads();

    // Block exclusive prefix over 1024 cells: 4 per thread + warp scan + cross-warp
    {
        const int base = tid * 4;
        int c0 = cnt[base], c1 = cnt[base + 1], c2 = cnt[base + 2], c3 = cnt[base + 3];
        int tot = c0 + c1 + c2 + c3;
        int inc = tot;
        #pragma unroll
        for (int o = 1; o < 32; o <<= 1) {
            int n = __shfl_up_sync(0xFFFFFFFFu, inc, o);
            if ((tid & 31) >= o) inc += n;
        }
        int pre = inc - tot;
        if ((tid & 31) == 31) wtot[tid >> 5] = inc;
        __syncthreads();
        if (tid == 0) {
            int r = 0;
            #pragma unroll
            for (int w = 0; w < 8; w++) { int t = wtot[w]; wtot[w] = r; r += t; }
        }
        __syncthreads();
        int off = pre + wtot[tid >> 5];
        int p0 = off, p1 = p0 + c0, p2 = p1 + c1, p3 = p2 + c2;
        ofs[base] = p0; ofs[base + 1] = p1; ofs[base + 2] = p2; ofs[base + 3] = p3;
        g_cellstart[c][base] = p0;     g_cellstart[c][base + 1] = p1;
        g_cellstart[c][base + 2] = p2; g_cellstart[c][base + 3] = p3;
        if (tid == 255) g_cellstart[c][NCELL] = p3 + c3;
    }
    __syncthreads();

    #pragma unroll
    for (int i = tid; i < NPTS; i += 256) {
        float x = src[3 * i], y = src[3 * i + 1], z = src[3 * i + 2];
        float w = fmaf(x, x, fmaf(y, y, z * z));
        int pos = atomicAdd(&ofs[cell_of(x, y)], 1);
        g_sorted[c][pos] = make_float4(x, y, z, w);
    }
}

// ---------------- Kernel 2: copy + warp-uniform 2D-pruned NN ----------------
struct Smem {
    float4 tgt[NPTS];            // 64 KB
    int    cst[NCELL + 1];       // 4.1 KB
    float  warpsums[NWARPS];
    unsigned int s_done;
};

__global__ __launch_bounds__(THREADS) void search_kernel(float* __restrict__ out)
{
    extern __shared__ char smem_raw[];
    Smem* s = (Smem*)smem_raw;
    const int tid = threadIdx.x;

    const int combo = blockIdx.x / SLICES;
    const int slice = blockIdx.x % SLICES;
    const int b     = combo >> 1;
    const int dir   = combo & 1;
    const int cs    = b * 2 + dir;
    const int ct    = b * 2 + (dir ^ 1);

    // Coalesced copy: sorted target cloud + cell prefix
    {
        const float4* __restrict__ g = g_sorted[ct];
        #pragma unroll
        for (int k = 0; k < NPTS / THREADS; k++)
            s->tgt[k * THREADS + tid] = g[k * THREADS + tid];
        for (int k = tid; k < NCELL + 1; k += THREADS)
            s->cst[k] = g_cellstart[ct][k];
    }

    // Source point: snake-sorted -> warp lanes are spatially compact
    const float4 p = g_sorted[cs][slice * THREADS + tid];
    const float mx = -2.0f * p.x, my = -2.0f * p.y, mz = -2.0f * p.z;
    const float p2 = p.w;

    __syncthreads();

    // Warp bbox of source points
    float bx0 = p.x, bx1 = p.x, by0 = p.y, by1 = p.y;
    #pragma unroll
    for (int o = 16; o > 0; o >>= 1) {
        bx0 = fminf(bx0, __shfl_xor_sync(0xFFFFFFFFu, bx0, o));
        bx1 = fmaxf(bx1, __shfl_xor_sync(0xFFFFFFFFu, bx1, o));
        by0 = fminf(by0, __shfl_xor_sync(0xFFFFFFFFu, by0, o));
        by1 = fmaxf(by1, __shfl_xor_sync(0xFFFFFFFFu, by1, o));
    }

    float best = INFINITY;     // min of (|t|^2 - 2 p.t); d2 = best + p2

    // Broadcast scan of a rectangular cell window (snake rows are contiguous)
    auto scan_win = [&](int wx0, int wx1, int wy0, int wy1) {
        for (int cy = wy0; cy <= wy1; cy++) {
            int a = (cy & 1) ? (GRID - 1 - wx1) : wx0;
            int e = (cy & 1) ? (GRID - 1 - wx0) : wx1;
            int s0 = s->cst[(cy << 5) + a];
            int e0 = s->cst[(cy << 5) + e + 1];
            #pragma unroll 4
            for (int j = s0; j < e0; j++) {
                float4 t = s->tgt[j];
                float v = fmaf(mx, t.x, fmaf(my, t.y, fmaf(mz, t.z, t.w)));
                best = fminf(best, v);
            }
        }
    };

    // Phase A: bbox + 1 ring; expand (rare) until some point seen
    int cx0 = max(clampg((int)((bx0 - XMIN) * INV_CELLW)) - 1, 0);
    int cx1 = min(clampg((int)((bx1 - XMIN) * INV_CELLW)) + 1, GRID - 1);
    int cy0 = max(clampg((int)((by0 - XMIN) * INV_CELLW)) - 1, 0);
    int cy1 = min(clampg((int)((by1 - XMIN) * INV_CELLW)) + 1, GRID - 1);
    while (true) {
        scan_win(cx0, cx1, cy0, cy1);
        if (best < 1e30f) break;                       // uniform: broadcast scan
        if (cx0 == 0 && cx1 == GRID - 1 && cy0 == 0 && cy1 == GRID - 1) break;
        cx0 = max(cx0 - 1, 0); cx1 = min(cx1 + 1, GRID - 1);
        cy0 = max(cy0 - 1, 0); cy1 = min(cy1 + 1, GRID - 1);
    }

    // Phase B: only if the bound ball can escape the scanned window
    float d2m = fmaxf(best + p2, 0.0f);
    #pragma unroll
    for (int o = 16; o > 0; o >>= 1)
        d2m = fmaxf(d2m, __shfl_xor_sync(0xFFFFFFFFu, d2m, o));
    float dcur = sqrtf(d2m) * 1.0001f + 1e-6f;

    float mgl = (cx0 == 0)        ? 1e30f : bx0 - (XMIN + cx0 * CELLW);
    float mgr = (cx1 == GRID - 1) ? 1e30f : (XMIN + (cx1 + 1) * CELLW) - bx1;
    float mgb = (cy0 == 0)        ? 1e30f : by0 - (XMIN + cy0 * CELLW);
    float mgt = (cy1 == GRID - 1) ? 1e30f : (XMIN + (cy1 + 1) * CELLW) - by1;
    float margin = fminf(fminf(mgl, mgr), fminf(mgb, mgt));

    if (dcur >= margin) {
        int fx0 = min(clampg((int)floorf((bx0 - dcur - XMIN) * INV_CELLW)), cx0);
        int fx1 = max(clampg((int)floorf((bx1 + dcur - XMIN) * INV_CELLW)), cx1);
        int fy0 = min(clampg((int)floorf((by0 - dcur - XMIN) * INV_CELLW)), cy0);
        int fy1 = max(clampg((int)floorf((by1 + dcur - XMIN) * INV_CELLW)), cy1);
        scan_win(fx0, fx1, fy0, fy1);   // idempotent min; rescans A (rare path)
    }

    float d = sqrtf(fmaxf(best + p2, 0.0f));

    // Reduction
    float acc = d;
    #pragma unroll
    for (int o = 16; o > 0; o >>= 1)
        acc += __shfl_xor_sync(0xFFFFFFFFu, acc, o);
    const int lane = tid & 31, wid = tid >> 5;
    if (lane == 0) s->warpsums[wid] = acc;
    __syncthreads();
    if (tid == 0) {
        float v = 0.0f;
        #pragma unroll
        for (int k = 0; k < NWARPS; k++) v += s->warpsums[k];
        atomicAdd(&g_sum, (double)v / ((double)BATCH * (double)NPTS));
    }

    // Ticket: last block publishes + resets
    __threadfence();
    if (tid == 0) s->s_done = atomicAdd(&g_tick, 1u);
    __syncthreads();
    if (s->s_done == NBLOCKS - 1 && tid == 0) {
        double total = atomicAdd(&g_sum, 0.0);
        out[0] = (float)total;
        g_sum  = 0.0;
        g_tick = 0;
    }
}

extern "C" void kernel_launch(void* const* d_in, const int* in_sizes, int n_in,
                              void* d_out, int out_size) {
    const float* pred = (const float*)d_in[0];
    const float* targ = (const float*)d_in[1];
    float* out = (float*)d_out;

    static bool attr_set = false;
    if (!attr_set) {
        cudaFuncSetAttribute(search_kernel,
                             cudaFuncAttributeMaxDynamicSharedMemorySize,
                             (int)sizeof(Smem));
        attr_set = true;
    }
    sort_kernel<<<NCLOUD, 256>>>(pred, targ);
    search_kernel<<<NBLOCKS, THREADS, sizeof(Smem)>>>(out);
}